// round 1
// baseline (speedup 1.0000x reference)
#include <cuda_runtime.h>
#include <math.h>

#define B_ 4096
#define D_ 256
#define SCALE_ 20.0f

// ---------------- scratch (device globals; no allocation) ----------------
__device__ float g_norm[4][(size_t)B_ * D_];     // normalized A, P, T, V (16 MB)
__device__ float g_rowpart[4][32][B_];           // per-pair, per-jtile partial row exp-sums
__device__ float g_colpart[4][32][B_];           // per-pair, per-itile partial col exp-sums
__device__ float g_diag[4][B_];                  // scaled diagonal scores
__device__ float g_blocksum[64];

// pair slots: 0=anchor, 1=positive, 2=ref_pos_text, 3=ref_pos_vision
// pairs p=0..3: (0,1) (0,2) (1,2) (1,3)  ->  x = p>>1, y = (p+3)>>1

// ---------------- 1) row-normalize the 4 used inputs ----------------
__global__ void normalize_kernel(const float* __restrict__ a, const float* __restrict__ b,
                                 const float* __restrict__ c, const float* __restrict__ d) {
    const float* src = blockIdx.y == 0 ? a : blockIdx.y == 1 ? b : blockIdx.y == 2 ? c : d;
    int row = blockIdx.x;
    float v = src[(size_t)row * D_ + threadIdx.x];
    float ss = v * v;
    #pragma unroll
    for (int o = 16; o > 0; o >>= 1) ss += __shfl_xor_sync(0xffffffffu, ss, o);
    __shared__ float ws[8];
    if ((threadIdx.x & 31) == 0) ws[threadIdx.x >> 5] = ss;
    __syncthreads();
    float tot = 0.f;
    #pragma unroll
    for (int i = 0; i < 8; i++) tot += ws[i];
    float r = rsqrtf(fmaxf(tot, 1e-24f));
    g_norm[blockIdx.y][(size_t)row * D_ + threadIdx.x] = v * r;
}

// ---------------- 2) diagonal scaled-cos per pair ----------------
__global__ void diag_kernel() {
    int p = blockIdx.y;
    int w = threadIdx.x >> 5, l = threadIdx.x & 31;
    int row = blockIdx.x * 8 + w;
    const float* __restrict__ x = g_norm[p >> 1]       + (size_t)row * D_;
    const float* __restrict__ y = g_norm[(p + 3) >> 1] + (size_t)row * D_;
    float s = 0.f;
    #pragma unroll
    for (int q = 0; q < 2; q++) {
        float4 xv = *(const float4*)(x + q * 128 + l * 4);
        float4 yv = *(const float4*)(y + q * 128 + l * 4);
        s += xv.x * yv.x + xv.y * yv.y + xv.z * yv.z + xv.w * yv.w;
    }
    #pragma unroll
    for (int o = 16; o > 0; o >>= 1) s += __shfl_xor_sync(0xffffffffu, s, o);
    if (l == 0) g_diag[p][row] = SCALE_ * s;
}

// ---------------- 3) fused GEMM (X * Y^T) + exp + row/col partial sums ----------------
// grid: (32 jtiles, 32 itiles, 4 pairs), block 256. CTA tile 128x128, K=256.
// Thread (tx,ty) = (t&15, t>>4) owns rows {ty+16i} x cols {tx+16j}, i,j in [0,8).
__global__ __launch_bounds__(256, 1)
void pair_gemm_kernel() {
    int p = blockIdx.z;
    const float* __restrict__ X = g_norm[p >> 1];
    const float* __restrict__ Y = g_norm[(p + 3) >> 1];
    int i0 = blockIdx.y * 128;
    int j0 = blockIdx.x * 128;

    __shared__ float As[128][36];   // row-major tile, pad to 36 floats
    __shared__ float Bs[128][36];

    int t  = threadIdx.x;
    int tx = t & 15;
    int ty = t >> 4;
    int lr = t >> 3;    // load: row-in-group 0..31
    int lg = t & 7;     // load: float4 group 0..7

    float acc[8][8];
    #pragma unroll
    for (int i = 0; i < 8; i++)
        #pragma unroll
        for (int j = 0; j < 8; j++) acc[i][j] = 0.f;

    for (int k0 = 0; k0 < D_; k0 += 32) {
        #pragma unroll
        for (int rr = 0; rr < 128; rr += 32) {
            float4 av = *(const float4*)&X[(size_t)(i0 + lr + rr) * D_ + k0 + lg * 4];
            float4 bv = *(const float4*)&Y[(size_t)(j0 + lr + rr) * D_ + k0 + lg * 4];
            *(float4*)&As[lr + rr][lg * 4] = av;
            *(float4*)&Bs[lr + rr][lg * 4] = bv;
        }
        __syncthreads();

        for (int kq = 0; kq < 32; kq += 4) {
            float4 a4[8], b4[8];
            #pragma unroll
            for (int i = 0; i < 8; i++) a4[i] = *(const float4*)&As[ty + 16 * i][kq];
            #pragma unroll
            for (int j = 0; j < 8; j++) b4[j] = *(const float4*)&Bs[tx + 16 * j][kq];
            #pragma unroll
            for (int i = 0; i < 8; i++)
                #pragma unroll
                for (int j = 0; j < 8; j++) {
                    acc[i][j] = fmaf(a4[i].x, b4[j].x, acc[i][j]);
                    acc[i][j] = fmaf(a4[i].y, b4[j].y, acc[i][j]);
                    acc[i][j] = fmaf(a4[i].z, b4[j].z, acc[i][j]);
                    acc[i][j] = fmaf(a4[i].w, b4[j].w, acc[i][j]);
                }
        }
        __syncthreads();
    }

    // exp + per-thread row/col partial sums (scores <= 20 -> exp <= 4.9e8, fp32-safe)
    float rsum[8], csum[8];
    #pragma unroll
    for (int i = 0; i < 8; i++) { rsum[i] = 0.f; csum[i] = 0.f; }
    #pragma unroll
    for (int i = 0; i < 8; i++)
        #pragma unroll
        for (int j = 0; j < 8; j++) {
            float e = __expf(SCALE_ * acc[i][j]);
            rsum[i] += e;
            csum[j] += e;
        }

    // in-tile reductions via smem reuse (last loop iteration ended in __syncthreads)
    float (*redR)[16] = reinterpret_cast<float(*)[16]>(&As[0][0]);
    float (*redC)[16] = reinterpret_cast<float(*)[16]>(&Bs[0][0]);
    #pragma unroll
    for (int i = 0; i < 8; i++) redR[ty + 16 * i][tx] = rsum[i];
    #pragma unroll
    for (int j = 0; j < 8; j++) redC[tx + 16 * j][ty] = csum[j];
    __syncthreads();

    if (t < 128) {
        float rs = 0.f, cs = 0.f;
        #pragma unroll
        for (int q = 0; q < 16; q++) { rs += redR[t][q]; cs += redC[t][q]; }
        g_rowpart[p][blockIdx.x][i0 + t] = rs;   // deterministic: unique (p, jtile, row)
        g_colpart[p][blockIdx.y][j0 + t] = cs;   // deterministic: unique (p, itile, col)
    }
}

// ---------------- 4) per-(pair,row) term + block reduce ----------------
__global__ void finalize1_kernel() {
    int idx = blockIdx.x * 256 + threadIdx.x;    // 0..16383
    int p = idx >> 12;
    int i = idx & (B_ - 1);
    float rs = 0.f, cs = 0.f;
    #pragma unroll
    for (int x = 0; x < 32; x++) {
        rs += g_rowpart[p][x][i];
        cs += g_colpart[p][x][i];
    }
    float term = 0.5f * (logf(rs) + logf(cs)) - g_diag[p][i];
    #pragma unroll
    for (int o = 16; o > 0; o >>= 1) term += __shfl_xor_sync(0xffffffffu, term, o);
    __shared__ float ws[8];
    if ((threadIdx.x & 31) == 0) ws[threadIdx.x >> 5] = term;
    __syncthreads();
    if (threadIdx.x == 0) {
        float s = 0.f;
        #pragma unroll
        for (int q = 0; q < 8; q++) s += ws[q];
        g_blocksum[blockIdx.x] = s;
    }
}

// ---------------- 5) final scalar ----------------
__global__ void finalize2_kernel(float* out, int out_size) {
    __shared__ float loss;
    if (threadIdx.x < 32) {
        float s = g_blocksum[threadIdx.x] + g_blocksum[threadIdx.x + 32];
        #pragma unroll
        for (int o = 16; o > 0; o >>= 1) s += __shfl_xor_sync(0xffffffffu, s, o);
        if (threadIdx.x == 0) loss = s / (float)(B_ * 2);
    }
    __syncthreads();
    for (int i = threadIdx.x; i < out_size; i += blockDim.x) out[i] = loss;
}

// ---------------- launch ----------------
extern "C" void kernel_launch(void* const* d_in, const int* in_sizes, int n_in,
                              void* d_out, int out_size) {
    (void)in_sizes; (void)n_in;
    const float* A = (const float*)d_in[0];  // anchor
    const float* P = (const float*)d_in[1];  // positive
    // d_in[2] = reference_anchor: unused by the reference
    const float* T = (const float*)d_in[3];  // reference_positive_text
    const float* V = (const float*)d_in[4];  // reference_positive_vision

    normalize_kernel<<<dim3(B_, 4), 256>>>(A, P, T, V);
    diag_kernel<<<dim3(B_ / 8, 4), 256>>>();
    pair_gemm_kernel<<<dim3(32, 32, 4), 256>>>();
    finalize1_kernel<<<64, 256>>>();
    finalize2_kernel<<<1, 128>>>((float*)d_out, out_size);
}

// round 3
// speedup vs baseline: 6.7191x; 6.7191x over previous
#include <cuda_runtime.h>
#include <cuda_bf16.h>
#include <math.h>
#include <stdint.h>

#define B_ 4096
#define D_ 256
#define SCALE_ 20.0f
#define NT_ 16          // N tiles (256 cols each)
#define MT_ 32          // M tiles (128 rows each)

// ------------- scratch (device globals; no allocation) -------------
// bf16 normalized inputs, K-chunked + SW128-preswizzled:
// slot s, kchunk c (64 k-vals), row r, k j -> byte off = ((c*4096+r)*128 + j*2) ^ ((off>>3)&0x70)
__device__ __align__(16) unsigned char g_nbf[4][4u * 4096u * 128u];   // 8 MB
__device__ float g_invnorm[4][B_];
__device__ float g_rowpart[4][NT_][B_];
__device__ float g_colpart[4][MT_][B_];
__device__ float g_diag[4][B_];
__device__ float g_blocksum[64];

// pair slots: 0=anchor, 1=positive, 2=ref_pos_text, 3=ref_pos_vision
// pairs p=0..3: (0,1) (0,2) (1,2) (1,3) -> x = p>>1, y = (p+3)>>1

// ------------- PTX helpers (all plain sm_90-level PTX; no 'a' features) -------------
__device__ __forceinline__ uint32_t smem_u32(const void* p) {
    uint32_t a;
    asm("{ .reg .u64 t; cvta.to.shared.u64 t, %1; cvt.u32.u64 %0, t; }" : "=r"(a) : "l"(p));
    return a;
}
__device__ __forceinline__ void mbar_init(uint32_t m, uint32_t cnt) {
    asm volatile("mbarrier.init.shared.b64 [%0], %1;" :: "r"(m), "r"(cnt) : "memory");
}
__device__ __forceinline__ void mbar_expect(uint32_t m, uint32_t tx) {
    asm volatile("mbarrier.arrive.expect_tx.shared.b64 _, [%0], %1;" :: "r"(m), "r"(tx) : "memory");
}
__device__ __forceinline__ void mbar_wait(uint32_t m, uint32_t ph) {
    asm volatile(
        "{\n\t.reg .pred P;\n"
        "WL_%=:\n\t"
        "mbarrier.try_wait.parity.shared.b64 P, [%0], %1;\n\t"
        "@!P bra WL_%=;\n"
        "}" :: "r"(m), "r"(ph) : "memory");
}
__device__ __forceinline__ void bulk_cp(uint32_t dst, const void* src, uint32_t bytes, uint32_t m) {
    asm volatile("cp.async.bulk.shared::cluster.global.mbarrier::complete_tx::bytes [%0], [%1], %2, [%3];"
                 :: "r"(dst), "l"(src), "r"(bytes), "r"(m) : "memory");
}
__device__ __forceinline__ void ldsm4(uint32_t* r, uint32_t addr) {
    asm volatile("ldmatrix.sync.aligned.m8n8.x4.shared.b16 {%0,%1,%2,%3}, [%4];"
                 : "=r"(r[0]), "=r"(r[1]), "=r"(r[2]), "=r"(r[3]) : "r"(addr));
}
__device__ __forceinline__ void mma16816(float* c, const uint32_t* a, uint32_t b0, uint32_t b1) {
    asm volatile("mma.sync.aligned.m16n8k16.row.col.f32.bf16.bf16.f32 "
                 "{%0,%1,%2,%3}, {%4,%5,%6,%7}, {%8,%9}, {%0,%1,%2,%3};"
                 : "+f"(c[0]), "+f"(c[1]), "+f"(c[2]), "+f"(c[3])
                 : "r"(a[0]), "r"(a[1]), "r"(a[2]), "r"(a[3]), "r"(b0), "r"(b1));
}

// ------------- 1) normalize + emit preswizzled chunked bf16 -------------
__global__ void normalize_kernel(const float* __restrict__ a, const float* __restrict__ b,
                                 const float* __restrict__ c, const float* __restrict__ d) {
    const float* src = blockIdx.y == 0 ? a : blockIdx.y == 1 ? b : blockIdx.y == 2 ? c : d;
    int row = blockIdx.x;
    float v = src[(size_t)row * D_ + threadIdx.x];
    float ss = v * v;
    #pragma unroll
    for (int o = 16; o > 0; o >>= 1) ss += __shfl_xor_sync(0xffffffffu, ss, o);
    __shared__ float ws[8];
    if ((threadIdx.x & 31) == 0) ws[threadIdx.x >> 5] = ss;
    __syncthreads();
    float tot = 0.f;
    #pragma unroll
    for (int i = 0; i < 8; i++) tot += ws[i];
    float r = rsqrtf(fmaxf(tot, 1e-24f));
    if (threadIdx.x == 0) g_invnorm[blockIdx.y][row] = r;
    uint32_t ch = threadIdx.x >> 6, j = threadIdx.x & 63;
    uint32_t off = (uint32_t)(ch * 4096u + row) * 128u + j * 2u;
    uint32_t sw = off ^ ((off >> 3) & 0x70u);
    *(__nv_bfloat16*)&g_nbf[blockIdx.y][sw] = __float2bfloat16(v * r);
}

// ------------- 2) diagonal scaled-cos per pair (fp32, exact) -------------
__global__ void diag_kernel(const float* __restrict__ a, const float* __restrict__ b,
                            const float* __restrict__ c, const float* __restrict__ d) {
    int p = blockIdx.y;
    int sx = p >> 1, sy = (p + 3) >> 1;
    const float* X = sx == 0 ? a : b;
    const float* Y = sy == 1 ? b : sy == 2 ? c : d;
    int w = threadIdx.x >> 5, l = threadIdx.x & 31;
    int row = blockIdx.x * 8 + w;
    const float* __restrict__ x = X + (size_t)row * D_;
    const float* __restrict__ y = Y + (size_t)row * D_;
    float s = 0.f;
    #pragma unroll
    for (int q = 0; q < 2; q++) {
        float4 xv = *(const float4*)(x + q * 128 + l * 4);
        float4 yv = *(const float4*)(y + q * 128 + l * 4);
        s += xv.x * yv.x + xv.y * yv.y + xv.z * yv.z + xv.w * yv.w;
    }
    #pragma unroll
    for (int o = 16; o > 0; o >>= 1) s += __shfl_xor_sync(0xffffffffu, s, o);
    if (l == 0) g_diag[p][row] = SCALE_ * s * g_invnorm[sx][row] * g_invnorm[sy][row];
}

// ------------- 3) HMMA GEMM + exp + row/col partial sums -------------
// grid (NT_=16, MT_=32, 4 pairs), 512 threads (2x8 warps, warp tile 64x32).
// CTA tile 128(M) x 256(N), K=256 in 4 chunks of 64; double-buffered bulk copies.
// Dyn SMEM (1024-aligned): [A0 16K][B0 32K][A1 16K][B1 32K] = 96K (+1K align pad)
#define SMEM_DYN_ (98304 + 1024)

__global__ __launch_bounds__(512, 1) void pair_gemm_mma() {
    extern __shared__ __align__(16) unsigned char dyn_smem[];
    __shared__ __align__(8) unsigned long long s_mbar[2];

    const int tid  = threadIdx.x;
    const int wid  = tid >> 5, lane = tid & 31;
    const int wm   = wid >> 3;            // 0..1  (M)
    const int wn   = wid & 7;             // 0..7  (N)
    const int p    = blockIdx.z;
    const int i0   = blockIdx.y * 128;
    const int j0   = blockIdx.x * 256;
    const unsigned char* Abase = g_nbf[p >> 1];
    const unsigned char* Bbase = g_nbf[(p + 3) >> 1];

    const uint32_t sbase = (smem_u32(dyn_smem) + 1023u) & ~1023u;
    uint32_t mfull[2] = {smem_u32(&s_mbar[0]), smem_u32(&s_mbar[1])};

    if (tid == 0) {
        mbar_init(mfull[0], 1u);
        mbar_init(mfull[1], 1u);
    }
    __syncthreads();

    if (tid == 0) {   // prologue: load chunks 0 and 1 (both buffers free)
        #pragma unroll
        for (int c = 0; c < 2; c++) {
            mbar_expect(mfull[c], 49152u);
            bulk_cp(sbase + c * 49152u,          Abase + (size_t)(c * 4096 + i0) * 128u, 16384u, mfull[c]);
            bulk_cp(sbase + c * 49152u + 16384u, Bbase + (size_t)(c * 4096 + j0) * 128u, 32768u, mfull[c]);
        }
    }

    // per-lane ldmatrix address components
    // A: lanes 0-15 rows, 16-31 rows w/ kbyte+16 (matches a0,a1,a2,a3 frag order)
    int a_row[4], a_xr[4];
    #pragma unroll
    for (int mi = 0; mi < 4; mi++) {
        int r = wm * 64 + mi * 16 + (lane & 15);
        a_row[mi] = r * 128;
        a_xr[mi] = (r & 7) << 4;
    }
    const int a_lk = (lane & 16) ? 16 : 0;
    // B: nblock pairs; lanes: (lane&7)=row-in-8, lane&16 -> +8 rows, lane&8 -> kbyte+16
    int b_row[2], b_xr[2];
    #pragma unroll
    for (int n2 = 0; n2 < 2; n2++) {
        int r = wn * 32 + n2 * 16 + (lane & 7) + ((lane & 16) ? 8 : 0);
        b_row[n2] = r * 128;
        b_xr[n2] = (r & 7) << 4;
    }
    const int b_lk = (lane & 8) ? 16 : 0;

    float acc[4][4][4];
    #pragma unroll
    for (int mi = 0; mi < 4; mi++)
        #pragma unroll
        for (int ni = 0; ni < 4; ni++)
            #pragma unroll
            for (int q = 0; q < 4; q++) acc[mi][ni][q] = 0.f;

    #pragma unroll
    for (int c = 0; c < 4; c++) {
        const uint32_t abuf = sbase + (uint32_t)(c & 1) * 49152u;
        const uint32_t bbuf = abuf + 16384u;
        mbar_wait(mfull[c & 1], (c >> 1) & 1);

        #pragma unroll
        for (int ks = 0; ks < 4; ks++) {
            const int kb = ks * 32;
            uint32_t a[4][4], b[2][4];
            #pragma unroll
            for (int mi = 0; mi < 4; mi++)
                ldsm4(a[mi], abuf + a_row[mi] + ((kb + a_lk) ^ a_xr[mi]));
            #pragma unroll
            for (int n2 = 0; n2 < 2; n2++)
                ldsm4(b[n2], bbuf + b_row[n2] + ((kb + b_lk) ^ b_xr[n2]));
            #pragma unroll
            for (int mi = 0; mi < 4; mi++)
                #pragma unroll
                for (int ni = 0; ni < 4; ni++)
                    mma16816(acc[mi][ni], a[mi], b[ni >> 1][(ni & 1) * 2], b[ni >> 1][(ni & 1) * 2 + 1]);
        }
        __syncthreads();   // all warps done reading buf (c&1)
        if (tid == 0 && c + 2 < 4) {
            mbar_expect(mfull[c & 1], 49152u);
            bulk_cp(sbase + (uint32_t)(c & 1) * 49152u,
                    Abase + (size_t)((c + 2) * 4096 + i0) * 128u, 16384u, mfull[c & 1]);
            bulk_cp(sbase + (uint32_t)(c & 1) * 49152u + 16384u,
                    Bbase + (size_t)((c + 2) * 4096 + j0) * 128u, 32768u, mfull[c & 1]);
        }
    }

    // ---- epilogue: exp + in-register reductions ----
    // C frag: q0=(r,c) q1=(r,c+1) q2=(r+8,c) q3=(r+8,c+1); r = lane>>2, c = (lane&3)*2
    float rs0[4], rs1[4], cs0[4], cs1[4];
    #pragma unroll
    for (int i = 0; i < 4; i++) { rs0[i] = rs1[i] = cs0[i] = cs1[i] = 0.f; }
    #pragma unroll
    for (int mi = 0; mi < 4; mi++)
        #pragma unroll
        for (int ni = 0; ni < 4; ni++) {
            float e0 = __expf(SCALE_ * acc[mi][ni][0]);
            float e1 = __expf(SCALE_ * acc[mi][ni][1]);
            float e2 = __expf(SCALE_ * acc[mi][ni][2]);
            float e3 = __expf(SCALE_ * acc[mi][ni][3]);
            rs0[mi] += e0 + e1;  rs1[mi] += e2 + e3;
            cs0[ni] += e0 + e2;  cs1[ni] += e1 + e3;
        }
    // rows: combine the 4 lanes of a quad (different cols)
    #pragma unroll
    for (int mi = 0; mi < 4; mi++) {
        rs0[mi] += __shfl_xor_sync(0xffffffffu, rs0[mi], 1);
        rs0[mi] += __shfl_xor_sync(0xffffffffu, rs0[mi], 2);
        rs1[mi] += __shfl_xor_sync(0xffffffffu, rs1[mi], 1);
        rs1[mi] += __shfl_xor_sync(0xffffffffu, rs1[mi], 2);
    }
    // cols: combine across quads (different rows)
    #pragma unroll
    for (int ni = 0; ni < 4; ni++) {
        #pragma unroll
        for (int h = 4; h <= 16; h <<= 1) {
            cs0[ni] += __shfl_xor_sync(0xffffffffu, cs0[ni], h);
            cs1[ni] += __shfl_xor_sync(0xffffffffu, cs1[ni], h);
        }
    }

    float* rowred = (float*)dyn_smem;        // [128][8]  (wn slices of N)
    float* colred = rowred + 128 * 8;        // [256][2]  (wm slices of M)
    __syncthreads();                          // everyone past tile reads
    if ((lane & 3) == 0) {
        #pragma unroll
        for (int mi = 0; mi < 4; mi++) {
            int r = wm * 64 + mi * 16 + (lane >> 2);
            rowred[r * 8 + wn] = rs0[mi];
            rowred[(r + 8) * 8 + wn] = rs1[mi];
        }
    }
    if (lane < 4) {
        #pragma unroll
        for (int ni = 0; ni < 4; ni++) {
            int cbase = wn * 32 + ni * 8 + lane * 2;
            colred[cbase * 2 + wm] = cs0[ni];
            colred[(cbase + 1) * 2 + wm] = cs1[ni];
        }
    }
    __syncthreads();
    if (tid < 128) {
        float s = 0.f;
        #pragma unroll
        for (int q = 0; q < 8; q++) s += rowred[tid * 8 + q];
        g_rowpart[p][blockIdx.x][i0 + tid] = s;
    } else if (tid < 384) {
        int cjj = tid - 128;
        g_colpart[p][blockIdx.y][j0 + cjj] = colred[cjj * 2] + colred[cjj * 2 + 1];
    }
}

// ------------- 4) per-(pair,row) term + block reduce -------------
__global__ void finalize1_kernel() {
    int idx = blockIdx.x * 256 + threadIdx.x;    // 0..16383
    int p = idx >> 12;
    int i = idx & (B_ - 1);
    float rs = 0.f, cs = 0.f;
    #pragma unroll
    for (int x = 0; x < NT_; x++) rs += g_rowpart[p][x][i];
    #pragma unroll
    for (int x = 0; x < MT_; x++) cs += g_colpart[p][x][i];
    float term = 0.5f * (logf(rs) + logf(cs)) - g_diag[p][i];
    #pragma unroll
    for (int o = 16; o > 0; o >>= 1) term += __shfl_xor_sync(0xffffffffu, term, o);
    __shared__ float ws[8];
    if ((threadIdx.x & 31) == 0) ws[threadIdx.x >> 5] = term;
    __syncthreads();
    if (threadIdx.x == 0) {
        float s = 0.f;
        #pragma unroll
        for (int q = 0; q < 8; q++) s += ws[q];
        g_blocksum[blockIdx.x] = s;
    }
}

// ------------- 5) final scalar -------------
__global__ void finalize2_kernel(float* out, int out_size) {
    __shared__ float loss;
    if (threadIdx.x < 32) {
        float s = g_blocksum[threadIdx.x] + g_blocksum[threadIdx.x + 32];
        #pragma unroll
        for (int o = 16; o > 0; o >>= 1) s += __shfl_xor_sync(0xffffffffu, s, o);
        if (threadIdx.x == 0) loss = s / (float)(B_ * 2);
    }
    __syncthreads();
    for (int i = threadIdx.x; i < out_size; i += blockDim.x) out[i] = loss;
}

// ------------- launch -------------
extern "C" void kernel_launch(void* const* d_in, const int* in_sizes, int n_in,
                              void* d_out, int out_size) {
    (void)in_sizes; (void)n_in;
    const float* A = (const float*)d_in[0];  // anchor
    const float* P = (const float*)d_in[1];  // positive
    // d_in[2] = reference_anchor: unused by the reference
    const float* T = (const float*)d_in[3];  // reference_positive_text
    const float* V = (const float*)d_in[4];  // reference_positive_vision

    cudaFuncSetAttribute(pair_gemm_mma, cudaFuncAttributeMaxDynamicSharedMemorySize, SMEM_DYN_);

    normalize_kernel<<<dim3(B_, 4), 256>>>(A, P, T, V);
    diag_kernel<<<dim3(B_ / 8, 4), 256>>>(A, P, T, V);
    pair_gemm_mma<<<dim3(NT_, MT_, 4), 512, SMEM_DYN_>>>();
    finalize1_kernel<<<64, 256>>>();
    finalize2_kernel<<<1, 128>>>((float*)d_out, out_size);
}